// round 2
// baseline (speedup 1.0000x reference)
#include <cuda_runtime.h>

// LSTM scan: T=2048, B=4096, IN_S=1, H=20, OUT_S=1, no biases.
// Round 2: fp32x2-packed gate math (fma.rn.f32x2), row-pair per thread
// (k, k+10), 10 threads per batch element, grid=128 blocks x 320 threads
// = exactly 1 block per SM (single wave, balanced).

#define TSTEPS 2048
#define BATCH  4096
#define H      20
#define HP     10            // row pairs per batch element (threads per batch)
#define BPB    32            // batch elements per block
#define TPB    (BPB * HP)    // 320 threads
#define CHUNK  64
#define NBLK   (BATCH / BPB) // 128 blocks

union F2U { float2 f2; unsigned long long u; };

__device__ __forceinline__ float2 ffma2(float2 a, float2 b, float2 c) {
    F2U A, B, C, D; A.f2 = a; B.f2 = b; C.f2 = c;
    asm("fma.rn.f32x2 %0, %1, %2, %3;" : "=l"(D.u) : "l"(A.u), "l"(B.u), "l"(C.u));
    return D.f2;
}
__device__ __forceinline__ float2 fmul2(float2 a, float2 b) {
    F2U A, B, D; A.f2 = a; B.f2 = b;
    asm("mul.rn.f32x2 %0, %1, %2;" : "=l"(D.u) : "l"(A.u), "l"(B.u));
    return D.f2;
}

__device__ __forceinline__ float sigf(float x) {
    return __fdividef(1.0f, 1.0f + __expf(-x));
}
__device__ __forceinline__ float tanh_f(float x) {
    return 1.0f - __fdividef(2.0f, __expf(2.0f * x) + 1.0f);
}
__device__ __forceinline__ float2 sig2(float2 x) {
    return make_float2(sigf(x.x), sigf(x.y));
}
__device__ __forceinline__ float2 tanh2(float2 x) {
    return make_float2(tanh_f(x.x), tanh_f(x.y));
}

__global__ void __launch_bounds__(TPB, 1)
lstm_scan_kernel(const float* __restrict__ u,     // [T, B, 1]
                 const float* __restrict__ Wih,   // [80, 1]
                 const float* __restrict__ Whh,   // [80, 20]
                 const float* __restrict__ Wout,  // [1, 20]
                 float* __restrict__ out)         // [T, B, 1]
{
    // h stored as DUPLICATED pairs: h_sh[buf][b][j] = (h_j, h_j), so a float4
    // read at [b][2q] yields two dup-pairs ready for fma.rn.f32x2 multipliers.
    __shared__ __align__(16) float2 h_sh[2][BPB][H];
    __shared__ float u_sh[CHUNK][BPB];
    __shared__ float y_sh[CHUNK][BPB];
    __shared__ float wout_sh[H];

    const int tid = threadIdx.x;
    const int bl  = tid / HP;     // local batch index 0..31
    const int kk  = tid % HP;     // row-pair index: handles rows kk and kk+10
    const int b0  = blockIdx.x * BPB;

    // Packed weights: w2[g][j] = (Whh[g*H+kk][j], Whh[g*H+kk+10][j]) : 160 regs
    float2 w2[4][H];
    float2 wih2[4];
#pragma unroll
    for (int g = 0; g < 4; g++) {
        wih2[g] = make_float2(Wih[g * H + kk], Wih[g * H + kk + 10]);
#pragma unroll
        for (int j = 0; j < H; j++)
            w2[g][j] = make_float2(Whh[(g * H + kk) * H + j],
                                   Whh[(g * H + kk + 10) * H + j]);
    }
    if (tid < H) wout_sh[tid] = Wout[tid];

    h_sh[0][bl][kk]      = make_float2(0.0f, 0.0f);
    h_sh[0][bl][kk + 10] = make_float2(0.0f, 0.0f);
    float2 c2 = make_float2(0.0f, 0.0f);
    int pb = 0;

#pragma unroll 1
    for (int tc = 0; tc < TSTEPS / CHUNK; tc++) {
        __syncthreads();  // prev chunk y_sh complete; u_sh reads done

        if (tc > 0) {
            const int t0p = (tc - 1) * CHUNK;
#pragma unroll 1
            for (int e = tid; e < CHUNK * BPB; e += TPB) {
                const int r = e >> 5, cc = e & 31;
                out[(t0p + r) * BATCH + b0 + cc] = y_sh[r][cc];
            }
        }
        {
            const int t0 = tc * CHUNK;
#pragma unroll 1
            for (int e = tid; e < CHUNK * BPB; e += TPB) {
                const int r = e >> 5, cc = e & 31;
                u_sh[r][cc] = u[(t0 + r) * BATCH + b0 + cc];
            }
        }
        __syncthreads();

#pragma unroll 1
        for (int tt = 0; tt < CHUNK; tt++) {
            const float x = u_sh[tt][bl];
            const float2 x2 = make_float2(x, x);

            float2 ai = fmul2(x2, wih2[0]);
            float2 af = fmul2(x2, wih2[1]);
            float2 ag = fmul2(x2, wih2[2]);
            float2 ao = fmul2(x2, wih2[3]);

            const float4* hv4 = reinterpret_cast<const float4*>(&h_sh[pb][bl][0]);
#pragma unroll
            for (int q = 0; q < H / 2; q++) {
                float4 v = hv4[q];                       // dup pairs for j=2q, 2q+1
                float2 p0 = make_float2(v.x, v.y);
                float2 p1 = make_float2(v.z, v.w);
                ai = ffma2(p0, w2[0][2 * q], ai);
                af = ffma2(p0, w2[1][2 * q], af);
                ag = ffma2(p0, w2[2][2 * q], ag);
                ao = ffma2(p0, w2[3][2 * q], ao);
                ai = ffma2(p1, w2[0][2 * q + 1], ai);
                af = ffma2(p1, w2[1][2 * q + 1], af);
                ag = ffma2(p1, w2[2][2 * q + 1], ag);
                ao = ffma2(p1, w2[3][2 * q + 1], ao);
            }

            const float2 ig = sig2(ai);
            const float2 fg = sig2(af);
            const float2 gg = tanh2(ag);
            const float2 og = sig2(ao);
            c2 = ffma2(fg, c2, fmul2(ig, gg));
            const float2 h2 = fmul2(og, tanh2(c2));

            h_sh[pb ^ 1][bl][kk]      = make_float2(h2.x, h2.x);
            h_sh[pb ^ 1][bl][kk + 10] = make_float2(h2.y, h2.y);
            __syncthreads();

            if (kk == 0) {
                // y_t = h_t . w_out  (read dup pairs: .x and .z are h values)
                const float4* hv = reinterpret_cast<const float4*>(&h_sh[pb ^ 1][bl][0]);
                float y = 0.0f;
#pragma unroll
                for (int q = 0; q < H / 2; q++) {
                    float4 v = hv[q];
                    y = fmaf(v.x, wout_sh[2 * q], y);
                    y = fmaf(v.z, wout_sh[2 * q + 1], y);
                }
                y_sh[tt][bl] = y;
            }
            pb ^= 1;
        }
    }

    __syncthreads();
    {
        const int t0p = (TSTEPS / CHUNK - 1) * CHUNK;
#pragma unroll 1
        for (int e = tid; e < CHUNK * BPB; e += TPB) {
            const int r = e >> 5, cc = e & 31;
            out[(t0p + r) * BATCH + b0 + cc] = y_sh[r][cc];
        }
    }
}

extern "C" void kernel_launch(void* const* d_in, const int* in_sizes, int n_in,
                              void* d_out, int out_size) {
    const float* u    = (const float*)d_in[0];  // [2048, 4096, 1]
    const float* Wih  = (const float*)d_in[1];  // [80, 1]
    const float* Whh  = (const float*)d_in[2];  // [80, 20]
    const float* Wout = (const float*)d_in[3];  // [1, 20]
    float* out = (float*)d_out;                 // [2048, 4096, 1]

    lstm_scan_kernel<<<NBLK, TPB>>>(u, Wih, Whh, Wout, out);
}

// round 3
// speedup vs baseline: 1.4067x; 1.4067x over previous
#include <cuda_runtime.h>

// LSTM scan: T=2048, B=4096, IN_S=1, H=20, OUT_S=1, no biases.
// Round 3: gate-pair fp32x2 packing. Thread = (batch, k) computes gates
// (i,f) and (g,o) as two packed f32x2 accumulators. Weights are
// (W_i[k][j], W_f[k][j]) pairs -> only 80 weight regs, FMA issue halved vs
// scalar. h exchanged via SMEM as duplicated pairs (h,h) so one float4 read
// yields two ready multipliers. Grid 293 x 280 = 2 blocks/SM, single wave,
// two independent barrier groups per SM.

#define TSTEPS 2048
#define BATCH  4096
#define H      20
#define BPB    14            // batch elements per block
#define TPB    (BPB * H)     // 280 threads
#define CHUNK  64
#define NBLK   ((BATCH + BPB - 1) / BPB)  // 293 blocks

union F2U { float2 f2; unsigned long long u; };

__device__ __forceinline__ float2 ffma2(float2 a, float2 b, float2 c) {
    F2U A, B, C, D; A.f2 = a; B.f2 = b; C.f2 = c;
    asm("fma.rn.f32x2 %0, %1, %2, %3;" : "=l"(D.u) : "l"(A.u), "l"(B.u), "l"(C.u));
    return D.f2;
}
__device__ __forceinline__ float2 fmul2(float2 a, float2 b) {
    F2U A, B, D; A.f2 = a; B.f2 = b;
    asm("mul.rn.f32x2 %0, %1, %2;" : "=l"(D.u) : "l"(A.u), "l"(B.u));
    return D.f2;
}

__device__ __forceinline__ float sigf(float x) {
    return __fdividef(1.0f, 1.0f + __expf(-x));
}
__device__ __forceinline__ float tanh_f(float x) {
    return 1.0f - __fdividef(2.0f, __expf(2.0f * x) + 1.0f);
}

__global__ void __launch_bounds__(TPB, 2)
lstm_scan_kernel(const float* __restrict__ u,     // [T, B, 1]
                 const float* __restrict__ Wih,   // [80, 1]
                 const float* __restrict__ Whh,   // [80, 20]
                 const float* __restrict__ Wout,  // [1, 20]
                 float* __restrict__ out)         // [T, B, 1]
{
    // h stored as DUPLICATED pairs: h_sh[buf][b][j] = (h_j, h_j); a float4
    // read at [b][2q] yields two dup-pair multipliers for fma.rn.f32x2.
    __shared__ __align__(16) float2 h_sh[2][BPB][H];
    __shared__ float u_sh[CHUNK][BPB];
    __shared__ float y_sh[CHUNK][BPB];
    __shared__ float wout_sh[H];

    const int tid = threadIdx.x;
    const int bl  = tid / H;      // local batch 0..13
    const int k   = tid % H;      // hidden index 0..19
    const int b0  = blockIdx.x * BPB;
    const bool active = (b0 + bl) < BATCH;

    // Gate-pair packed weights: 80 float regs total.
    float2 wif[H];   // (W_i[k][j], W_f[k][j])
    float2 wgo[H];   // (W_g[k][j], W_o[k][j])
#pragma unroll
    for (int j = 0; j < H; j++) {
        wif[j] = make_float2(Whh[(k) * H + j],      Whh[(H + k) * H + j]);
        wgo[j] = make_float2(Whh[(2 * H + k) * H + j], Whh[(3 * H + k) * H + j]);
    }
    const float2 wih_if = make_float2(Wih[k],         Wih[H + k]);
    const float2 wih_go = make_float2(Wih[2 * H + k], Wih[3 * H + k]);
    if (tid < H) wout_sh[tid] = Wout[tid];

    h_sh[0][bl][k] = make_float2(0.0f, 0.0f);
    float c = 0.0f;
    int pb = 0;

#pragma unroll 1
    for (int tc = 0; tc < TSTEPS / CHUNK; tc++) {
        __syncthreads();  // prev chunk y_sh complete; u_sh reads done

        if (tc > 0) {
            const int t0p = (tc - 1) * CHUNK;
#pragma unroll 1
            for (int e = tid; e < CHUNK * BPB; e += TPB) {
                const int r = e / BPB, cc = e % BPB;
                if (b0 + cc < BATCH)
                    out[(t0p + r) * BATCH + b0 + cc] = y_sh[r][cc];
            }
        }
        {
            const int t0 = tc * CHUNK;
#pragma unroll 1
            for (int e = tid; e < CHUNK * BPB; e += TPB) {
                const int r = e / BPB, cc = e % BPB;
                u_sh[r][cc] = (b0 + cc < BATCH) ? u[(t0 + r) * BATCH + b0 + cc] : 0.0f;
            }
        }
        __syncthreads();

#pragma unroll 1
        for (int tt = 0; tt < CHUNK; tt++) {
            const float x = u_sh[tt][bl];
            const float2 x2 = make_float2(x, x);

            float2 aif = fmul2(x2, wih_if);   // (a_i, a_f)
            float2 ago = fmul2(x2, wih_go);   // (a_g, a_o)

            const float4* hv4 = reinterpret_cast<const float4*>(&h_sh[pb][bl][0]);
#pragma unroll
            for (int q = 0; q < H / 2; q++) {
                float4 v = hv4[q];                  // dup pairs for j=2q, 2q+1
                float2 p0 = make_float2(v.x, v.y);
                float2 p1 = make_float2(v.z, v.w);
                aif = ffma2(p0, wif[2 * q], aif);
                ago = ffma2(p0, wgo[2 * q], ago);
                aif = ffma2(p1, wif[2 * q + 1], aif);
                ago = ffma2(p1, wgo[2 * q + 1], ago);
            }

            const float ig = sigf(aif.x);
            const float fg = sigf(aif.y);
            const float gg = tanh_f(ago.x);
            const float og = sigf(ago.y);
            c = fmaf(fg, c, ig * gg);
            const float h = og * tanh_f(c);

            h_sh[pb ^ 1][bl][k] = make_float2(h, h);
            __syncthreads();

            if (k == 0) {
                // y_t = h_t . w_out  (dup pairs: .x and .z carry h values)
                const float4* hv = reinterpret_cast<const float4*>(&h_sh[pb ^ 1][bl][0]);
                float y = 0.0f;
#pragma unroll
                for (int q = 0; q < H / 2; q++) {
                    float4 v = hv[q];
                    y = fmaf(v.x, wout_sh[2 * q], y);
                    y = fmaf(v.z, wout_sh[2 * q + 1], y);
                }
                y_sh[tt][bl] = y;
            }
            pb ^= 1;
        }
    }

    __syncthreads();
    {
        const int t0p = (TSTEPS / CHUNK - 1) * CHUNK;
#pragma unroll 1
        for (int e = tid; e < CHUNK * BPB; e += TPB) {
            const int r = e / BPB, cc = e % BPB;
            if (b0 + cc < BATCH)
                out[(t0p + r) * BATCH + b0 + cc] = y_sh[r][cc];
        }
    }
    (void)active;
}

extern "C" void kernel_launch(void* const* d_in, const int* in_sizes, int n_in,
                              void* d_out, int out_size) {
    const float* u    = (const float*)d_in[0];  // [2048, 4096, 1]
    const float* Wih  = (const float*)d_in[1];  // [80, 1]
    const float* Whh  = (const float*)d_in[2];  // [80, 20]
    const float* Wout = (const float*)d_in[3];  // [1, 20]
    float* out = (float*)d_out;                 // [2048, 4096, 1]

    lstm_scan_kernel<<<NBLK, TPB>>>(u, Wih, Whh, Wout, out);
}